// round 9
// baseline (speedup 1.0000x reference)
#include <cuda_runtime.h>

#define B  4
#define C  84
#define CR 80          // channels participating in max (84 - 4)
#define H  512
#define W  512
#define HW (H * W)

// Fused kernel: one block per (b, h) row, 512 threads = one per column x.
//
// Phase A: load center row's 84 channels into SMEM (168 KB) while computing
//          the 80-channel max in a register; stream halo rows h-1 / h+1 for
//          their 80-channel maxes only (these loads are adjacent blocks'
//          center rows -> L2 hits in the common case).
// Phase B: 3x3 NMS mask from the three probs rows in SMEM (zero-padded).
//          Reference semantics (window idx, center=4):
//            idx < 4 (row above + left)   -> p >  nb
//            idx > 4 (right + row below)  -> p >= nb
// Phase C: out = smem_row * mask for all 84 channels (no gmem re-read),
//          streaming stores.
//
// SMEM: 84*512 floats rowbuf + 3*(W+2) probs = 178,200 B -> 1 block/SM.

#define SMEM_BYTES (C * W * sizeof(float) + 3 * (W + 2) * sizeof(float))

__global__ void __launch_bounds__(512, 1) fused_nms_kernel(
    const float* __restrict__ points, float* __restrict__ out)
{
    extern __shared__ float smem[];
    float* rowbuf = smem;                       // [C][W]
    float* pr     = smem + C * W;               // [3][W+2], zero-padded halo cols

    const int h = blockIdx.x;
    const int b = blockIdx.y;
    const int x = threadIdx.x;                  // 0..511 (== W)

    const float* base = points + (size_t)b * C * HW + (size_t)h * W + x;

    // ---- Phase A: center row (84 ch -> smem, max over first 80) ----
    float mc;
    {
        float v0 = base[0];
        rowbuf[x] = v0;
        mc = v0;
    }
    #pragma unroll 14
    for (int c = 1; c < C; c++) {
        float v = base[(size_t)c * HW];
        rowbuf[c * W + x] = v;
        if (c < CR) mc = fmaxf(mc, v);
    }

    // ---- Halo rows: 80-channel max only (pad row == 0.0f) ----
    float mu = 0.0f;
    if (h > 0) {
        const float* up = base - W;
        mu = up[0];
        #pragma unroll 16
        for (int c = 1; c < CR; c++) mu = fmaxf(mu, up[(size_t)c * HW]);
    }
    float md = 0.0f;
    if (h < H - 1) {
        const float* dn = base + W;
        md = dn[0];
        #pragma unroll 16
        for (int c = 1; c < CR; c++) md = fmaxf(md, dn[(size_t)c * HW]);
    }

    // ---- Probs rows into smem with zero halo columns ----
    pr[0 * (W + 2) + 1 + x] = mu;
    pr[1 * (W + 2) + 1 + x] = mc;
    pr[2 * (W + 2) + 1 + x] = md;
    if (x < 3) {
        pr[x * (W + 2) + 0]     = 0.0f;
        pr[x * (W + 2) + W + 1] = 0.0f;
    }
    __syncthreads();

    // ---- Phase B: NMS mask for pixel x ----
    const float* r0 = pr;                       // row h-1
    const float* r1 = pr + (W + 2);             // row h
    const float* r2 = pr + 2 * (W + 2);         // row h+1
    float p = r1[x + 1];
    bool m =
        (p >  r0[x    ]) &&     // idx 0
        (p >  r0[x + 1]) &&     // idx 1
        (p >  r0[x + 2]) &&     // idx 2
        (p >  r1[x    ]) &&     // idx 3 (left)
        (p >= r1[x + 2]) &&     // idx 5 (right)
        (p >= r2[x    ]) &&     // idx 6
        (p >= r2[x + 1]) &&     // idx 7
        (p >= r2[x + 2]);       // idx 8
    float msk = m ? 1.0f : 0.0f;

    // ---- Phase C: multiply all 84 channels from smem, streaming stores ----
    float* obase = out + (size_t)b * C * HW + (size_t)h * W + x;
    #pragma unroll 14
    for (int c = 0; c < C; c++) {
        __stcs(obase + (size_t)c * HW, rowbuf[c * W + x] * msk);
    }
}

// ---------------------------------------------------------------------------
extern "C" void kernel_launch(void* const* d_in, const int* in_sizes, int n_in,
                              void* d_out, int out_size)
{
    const float* points = (const float*)d_in[0];
    float* out = (float*)d_out;

    // Opt into >48KB dynamic smem (idempotent; host-side attr, capture-safe).
    cudaFuncSetAttribute(fused_nms_kernel,
                         cudaFuncAttributeMaxDynamicSharedMemorySize,
                         (int)SMEM_BYTES);

    dim3 grid(H, B);   // blockIdx.x = h (adjacent h co-scheduled -> halo L2 hits)
    fused_nms_kernel<<<grid, 512, SMEM_BYTES>>>(points, out);
}

// round 10
// speedup vs baseline: 1.1272x; 1.1272x over previous
#include <cuda_runtime.h>

#define B   4
#define C   84
#define CR  80          // channels participating in max (84 - 4)
#define H   512
#define W   512
#define HW  (H * W)
#define TH  2           // rows per block
#define PRW (W + 8)     // probs row stride: left pad at [3], data [4..515], right pad [516]

// Fused NMS, low-smem variant.
//
// Block = (b, row-pair h0, h0+1), 512 threads.
// Phase A: 4 warp-groups of 128 threads each compute the 80-channel max for
//          one of rows h0-1 .. h0+2 (float4 per thread). Halo rows are
//          adjacent blocks' center rows -> L2 hits. Out-of-image rows = 0.
// Phase B: 3x3 NMS masks for the 2 center rows from smem probs.
//          Reference semantics (window idx, center=4):
//            idx < 4 (row above + left)  -> p >  nb
//            idx > 4 (right + row below) -> p >= nb
// Phase C: sparse multiply. Masked pixels write 0 with NO load; survivors
//          (~1/9) re-read points (L2-hot from Phase A) and copy. float2 per
//          thread, streaming stores.

__global__ void __launch_bounds__(512) fused_nms_kernel(
    const float* __restrict__ points, float* __restrict__ out)
{
    __shared__ float pr[TH + 2][PRW];   // probs rows h0-1..h0+2, zero-padded cols
    __shared__ float s_msk[TH][W];

    const int tid = threadIdx.x;
    const int h0  = blockIdx.x * TH;
    const int b   = blockIdx.y;

    // ---- Phase A: per-row channel max (rows h0-1 .. h0+2) ----
    {
        const int r  = tid >> 7;            // 0..3 -> global row h0-1+r
        const int x4 = (tid & 127) << 2;    // col0 of this thread's float4
        const int g  = h0 - 1 + r;

        float4 m4 = make_float4(0.f, 0.f, 0.f, 0.f);   // pad rows stay 0
        if (g >= 0 && g < H) {
            const float4* p4 = reinterpret_cast<const float4*>(
                points + (size_t)b * C * HW + (size_t)g * W + x4);
            m4 = __ldg(p4);
            #pragma unroll 8
            for (int c = 1; c < CR; c++) {
                float4 v = __ldg(p4 + (size_t)c * (HW / 4));
                m4.x = fmaxf(m4.x, v.x);
                m4.y = fmaxf(m4.y, v.y);
                m4.z = fmaxf(m4.z, v.z);
                m4.w = fmaxf(m4.w, v.w);
            }
        }
        *reinterpret_cast<float4*>(&pr[r][4 + x4]) = m4;   // 16B-aligned
        if (tid < TH + 2) {                  // zero halo columns
            pr[tid][3]     = 0.f;
            pr[tid][4 + W] = 0.f;
        }
    }
    __syncthreads();

    // ---- Phase B: NMS mask for the TH center rows, column x = tid ----
    {
        const int x = tid;
        #pragma unroll
        for (int i = 0; i < TH; i++) {
            float p = pr[i + 1][4 + x];
            bool m =
                (p >  pr[i    ][3 + x]) &&   // idx 0
                (p >  pr[i    ][4 + x]) &&   // idx 1
                (p >  pr[i    ][5 + x]) &&   // idx 2
                (p >  pr[i + 1][3 + x]) &&   // idx 3 (left)
                (p >= pr[i + 1][5 + x]) &&   // idx 5 (right)
                (p >= pr[i + 2][3 + x]) &&   // idx 6
                (p >= pr[i + 2][4 + x]) &&   // idx 7
                (p >= pr[i + 2][5 + x]);     // idx 8
            s_msk[i][x] = m ? 1.0f : 0.0f;
        }
    }
    __syncthreads();

    // ---- Phase C: sparse multiply, float2 per thread ----
    {
        const int i  = tid >> 8;             // which center row (0/1)
        const int c0 = (tid & 255) * 2;      // column pair
        const float m0 = s_msk[i][c0];
        const float m1 = s_msk[i][c0 + 1];
        const bool any = (m0 + m1) > 0.0f;

        const size_t off = (size_t)b * C * HW + (size_t)(h0 + i) * W + c0;
        const float2* ip = reinterpret_cast<const float2*>(points + off);
        float2*       op = reinterpret_cast<float2*>(out + off);

        #pragma unroll 4
        for (int c = 0; c < C; c++) {
            float2 v = make_float2(0.f, 0.f);
            if (any) {
                v = __ldg(ip + (size_t)c * (HW / 2));
                v.x *= m0;
                v.y *= m1;
            }
            __stcs(op + (size_t)c * (HW / 2), v);
        }
    }
}

// ---------------------------------------------------------------------------
extern "C" void kernel_launch(void* const* d_in, const int* in_sizes, int n_in,
                              void* d_out, int out_size)
{
    const float* points = (const float*)d_in[0];
    float* out = (float*)d_out;

    dim3 grid(H / TH, B);   // adjacent blockIdx.x co-scheduled -> halo L2 hits
    fused_nms_kernel<<<grid, 512>>>(points, out);
}

// round 11
// speedup vs baseline: 1.2706x; 1.1271x over previous
#include <cuda_runtime.h>
#include <math_constants.h>

#define B_   4
#define C_   84
#define CR_  80          // channels in the max (84 - 4)
#define H_   512
#define W_   512
#define HW_  (H_ * W_)

#define CW   128         // columns per block strip
#define TH   32          // output rows per block
#define NQ   4           // channel-quarter split
#define CPQ  21          // C / NQ   (full-row channels per quarter)
#define PPQ  20          // CR / NQ  (probs-only-row channels per quarter)
#define NTHREADS 512     // NQ * CW

#define PBS  130         // probs row stride: [0]=left halo, [1..128]=cols, [129]=right halo
#define SL(g) (((g) + 3) % 3)

// dynamic smem: rb[2][C][CW] + pb[3][PBS] + pm[NQ][CW]
#define SMEM_FLOATS (2 * C_ * CW + 3 * PBS + NQ * CW)
#define SMEM_BYTES  (SMEM_FLOATS * sizeof(float))

// ---------------------------------------------------------------------------
// Fused NMS, row-pipelined. Block owns a 128-col x 32-row strip of one batch.
// Per row-iteration:
//   load row g: 84 channels -> smem ring rb[g&1]; per-(quarter,col) partial
//     max -> pm; warps 0/1 compute the 2 halo-column 80-ch maxes via shuffle.
//   finalize: probs[g] = max over quarters (q==0 threads), into 3-deep ring pb.
//   mask row h (=g-1) from pb rows h-1,h,h+1 (reference semantics: strict >
//     for up-row+left, >= for right+down-row; zero padding), multiply rb[h&1]
//     from smem, streaming stores.
// Input is read from gmem EXACTLY ONCE (plus 2 probs-only halo rows / strip).
// ---------------------------------------------------------------------------
__global__ void __launch_bounds__(NTHREADS, 2) fused_nms_pipe(
    const float* __restrict__ points, float* __restrict__ out)
{
    extern __shared__ float smem[];
    float* rb = smem;                    // [2][C_][CW]
    float* pb = rb + 2 * C_ * CW;        // [3][PBS]
    float* pm = pb + 3 * PBS;            // [NQ][CW]

    const int tid = threadIdx.x;
    const int q   = tid >> 7;            // 0..3
    const int col = tid & (CW - 1);      // 0..127
    const int x0  = blockIdx.x * CW;
    const int h0  = blockIdx.y * TH;
    const int b   = blockIdx.z;
    const size_t bbase = (size_t)b * C_ * HW_;

    // ---- row loader ----------------------------------------------------
    auto load_row = [&](int g, bool full, int rbslot) {
        if (g < 0 || g >= H_) return;    // pad row: nothing to load
        const float* rowp = points + bbase + (size_t)g * W_ + x0 + col;
        float m = -CUDART_INF_F;
        if (full) {
            const int c0 = q * CPQ;
            float* rbq = rb + (rbslot * C_ + c0) * CW + col;
            #pragma unroll
            for (int i = 0; i < CPQ; i++) {
                float v = __ldg(rowp + (size_t)(c0 + i) * HW_);
                rbq[i * CW] = v;
                if (c0 + i < CR_) m = fmaxf(m, v);
            }
        } else {
            const int c0 = q * PPQ;
            #pragma unroll
            for (int i = 0; i < PPQ; i++)
                m = fmaxf(m, __ldg(rowp + (size_t)(c0 + i) * HW_));
        }
        pm[q * CW + col] = m;

        // halo columns: warp 0 -> x0-1, warp 1 -> x0+CW
        const int w = tid >> 5;
        if (w < 2) {
            const int lane = tid & 31;
            const int gx = (w == 0) ? (x0 - 1) : (x0 + CW);
            float hm = 0.0f;
            if (gx >= 0 && gx < W_) {
                const float* hp = points + bbase + (size_t)g * W_ + gx;
                hm = -CUDART_INF_F;
                #pragma unroll
                for (int k = 0; k < 3; k++) {
                    int c = lane + k * 32;
                    if (c < CR_) hm = fmaxf(hm, __ldg(hp + (size_t)c * HW_));
                }
                #pragma unroll
                for (int off = 16; off; off >>= 1)
                    hm = fmaxf(hm, __shfl_xor_sync(0xffffffffu, hm, off));
            }
            if (lane == 0) pb[SL(g) * PBS + ((w == 0) ? 0 : (CW + 1))] = hm;
        }
    };

    // ---- probs finalize (after sync on pm) ------------------------------
    auto finalize_row = [&](int g) {
        const int slot = SL(g) * PBS;
        if (g >= 0 && g < H_) {
            if (q == 0) {
                float v = fmaxf(fmaxf(pm[col], pm[CW + col]),
                                fmaxf(pm[2 * CW + col], pm[3 * CW + col]));
                pb[slot + 1 + col] = v;
            }
        } else {                          // zero pad row (incl. halo cols)
            if (tid < CW)           pb[slot + 1 + tid] = 0.0f;
            else if (tid == CW)     pb[slot + 0]       = 0.0f;
            else if (tid == CW + 1) pb[slot + CW + 1]  = 0.0f;
        }
    };

    // ---- prologue: probs for rows h0-1 and h0 ---------------------------
    load_row(h0 - 1, false, 0);
    __syncthreads();
    finalize_row(h0 - 1);
    __syncthreads();
    load_row(h0, true, h0 & 1);
    __syncthreads();
    finalize_row(h0);
    __syncthreads();

    // ---- main pipeline ---------------------------------------------------
    for (int h = h0; h < h0 + TH; h++) {
        const int gn = h + 1;
        load_row(gn, /*full=*/(gn < h0 + TH), gn & 1);
        __syncthreads();
        finalize_row(gn);
        __syncthreads();

        // mask row h (each thread computes its column's mask redundantly per q)
        {
            const int s0 = SL(h - 1) * PBS;
            const int s1 = SL(h)     * PBS;
            const int s2 = SL(h + 1) * PBS;
            const float p = pb[s1 + 1 + col];
            bool mok =
                (p >  pb[s0 + col    ]) &&   // (-1,-1)
                (p >  pb[s0 + col + 1]) &&   // (-1, 0)
                (p >  pb[s0 + col + 2]) &&   // (-1,+1)
                (p >  pb[s1 + col    ]) &&   // ( 0,-1)
                (p >= pb[s1 + col + 2]) &&   // ( 0,+1)
                (p >= pb[s2 + col    ]) &&   // (+1,-1)
                (p >= pb[s2 + col + 1]) &&   // (+1, 0)
                (p >= pb[s2 + col + 2]);     // (+1,+1)
            const float msk = mok ? 1.0f : 0.0f;

            const float* rbq = rb + ((h & 1) * C_ + q * CPQ) * CW + col;
            float* op = out + bbase + (size_t)h * W_ + x0 + col;
            #pragma unroll
            for (int i = 0; i < CPQ; i++)
                __stcs(op + (size_t)(q * CPQ + i) * HW_, rbq[i * CW] * msk);
        }
        __syncthreads();   // protect pb[SL(h-1)] and pm before next iteration
    }
}

// ---------------------------------------------------------------------------
extern "C" void kernel_launch(void* const* d_in, const int* in_sizes, int n_in,
                              void* d_out, int out_size)
{
    const float* points = (const float*)d_in[0];
    float* out = (float*)d_out;

    cudaFuncSetAttribute(fused_nms_pipe,
                         cudaFuncAttributeMaxDynamicSharedMemorySize,
                         (int)SMEM_BYTES);

    dim3 grid(W_ / CW, H_ / TH, B_);     // (4, 16, 4) = 256 blocks, 2/SM
    fused_nms_pipe<<<grid, NTHREADS, SMEM_BYTES>>>(points, out);
}

// round 12
// speedup vs baseline: 1.2870x; 1.0129x over previous
#include <cuda_runtime.h>
#include <math_constants.h>

#define B_   4
#define C_   84
#define CR_  80          // channels in the max (84 - 4)
#define H_   512
#define W_   512
#define HW_  (H_ * W_)

#define CW   64          // columns per block strip
#define TH   32          // output rows per block
#define NQ   4           // channel-quarter split
#define CPQ  21          // C / NQ   (full-row channels per quarter)
#define PPQ  20          // CR / NQ  (probs-only-row channels per quarter)
#define NT   256         // NQ * CW

#define SL(g) (((g) + 3) % 3)

// dynamic smem: rb[2][C][CW] + pbq[3][NQ][CW] + ph[3*2 (+pad)]
#define RB_FLOATS  (2 * C_ * CW)
#define PBQ_FLOATS (3 * NQ * CW)
#define SMEM_FLOATS (RB_FLOATS + PBQ_FLOATS + 8)
#define SMEM_BYTES  (SMEM_FLOATS * sizeof(float))

// ---------------------------------------------------------------------------
// Fused NMS, row-pipelined, 4 blocks/SM. Block owns a 64-col x 32-row strip.
// Per row-iteration (2 barriers):
//   load row g=h+1: quarter q loads its 21 channels -> rb ring slot (g&1),
//     per-(quarter,col) running max -> pbq ring slot SL(g); warps 0/1 compute
//     the two halo-column 80-ch maxes (shuffle-reduce) -> ph ring.
//   __syncthreads();
//   mask row h: combine 4 quarter maxes inline from pbq rows h-1,h,h+1
//     (reference: strict > for up-row + left, >= for right + down-row; zero
//     padding), multiply rb[h&1] from smem, streaming stores.
//   __syncthreads();
// Input read from gmem exactly once (+2 probs-only halo rows, +2 halo cols).
// ---------------------------------------------------------------------------
__global__ void __launch_bounds__(NT, 4) fused_nms_pipe4(
    const float* __restrict__ points, float* __restrict__ out)
{
    extern __shared__ float smem[];
    float* rb  = smem;                    // [2][C_][CW]
    float* pbq = rb + RB_FLOATS;          // [3][NQ][CW]
    float* ph  = pbq + PBQ_FLOATS;        // [3][2]

    const int tid = threadIdx.x;
    const int q   = tid >> 6;             // 0..3
    const int col = tid & (CW - 1);       // 0..63
    const int x0  = blockIdx.x * CW;
    const int h0  = blockIdx.y * TH;
    const int b   = blockIdx.z;
    const size_t bbase = (size_t)b * C_ * HW_;

    // ---- row loader ------------------------------------------------------
    auto load_row = [&](int g, bool full, int rbslot) {
        const int slot = SL(g);
        if (g < 0 || g >= H_) {           // zero pad row (probs = 0.0)
            pbq[(slot * NQ + q) * CW + col] = 0.0f;
            if (tid < 2) ph[slot * 2 + tid] = 0.0f;
            return;
        }
        const float* rowp = points + bbase + (size_t)g * W_ + x0 + col;
        float m = -CUDART_INF_F;
        if (full) {
            const int c0 = q * CPQ;
            float* rbq = rb + (rbslot * C_ + c0) * CW + col;
            #pragma unroll
            for (int i = 0; i < CPQ; i++) {
                float v = __ldg(rowp + (size_t)(c0 + i) * HW_);
                rbq[i * CW] = v;
                if (c0 + i < CR_) m = fmaxf(m, v);
            }
        } else {
            const int c0 = q * PPQ;
            #pragma unroll
            for (int i = 0; i < PPQ; i++)
                m = fmaxf(m, __ldg(rowp + (size_t)(c0 + i) * HW_));
        }
        pbq[(slot * NQ + q) * CW + col] = m;

        // halo columns: warp 0 -> x0-1, warp 1 -> x0+CW
        const int w = tid >> 5;
        if (w < 2) {
            const int lane = tid & 31;
            const int gx = (w == 0) ? (x0 - 1) : (x0 + CW);
            float hm = 0.0f;
            if (gx >= 0 && gx < W_) {
                const float* hp = points + bbase + (size_t)g * W_ + gx;
                hm = -CUDART_INF_F;
                #pragma unroll
                for (int k = 0; k < 3; k++) {
                    int c = lane + k * 32;
                    if (c < CR_) hm = fmaxf(hm, __ldg(hp + (size_t)c * HW_));
                }
                #pragma unroll
                for (int off = 16; off; off >>= 1)
                    hm = fmaxf(hm, __shfl_xor_sync(0xffffffffu, hm, off));
            }
            if (lane == 0) ph[slot * 2 + w] = hm;
        }
    };

    // combined probs at (ring slot s, strip col c), c may be -1 or CW
    auto P = [&](int s, int c) -> float {
        if (c < 0)    return ph[s * 2 + 0];
        if (c >= CW)  return ph[s * 2 + 1];
        const float* p0 = pbq + s * NQ * CW + c;
        return fmaxf(fmaxf(p0[0 * CW], p0[1 * CW]),
                     fmaxf(p0[2 * CW], p0[3 * CW]));
    };

    // ---- prologue: rows h0-1 (probs only) and h0 (full) ------------------
    load_row(h0 - 1, false, 0);
    load_row(h0, true, h0 & 1);

    // ---- main pipeline ---------------------------------------------------
    for (int h = h0; h < h0 + TH; h++) {
        const int gn = h + 1;
        load_row(gn, /*full=*/(gn < h0 + TH), gn & 1);
        __syncthreads();

        // mask row h (computed redundantly by each quarter for its columns)
        {
            const int s0 = SL(h - 1), s1 = SL(h), s2 = SL(h + 1);
            const float p = P(s1, col);
            bool mok =
                (p >  P(s0, col - 1)) &&   // (-1,-1)
                (p >  P(s0, col    )) &&   // (-1, 0)
                (p >  P(s0, col + 1)) &&   // (-1,+1)
                (p >  P(s1, col - 1)) &&   // ( 0,-1) left
                (p >= P(s1, col + 1)) &&   // ( 0,+1) right
                (p >= P(s2, col - 1)) &&   // (+1,-1)
                (p >= P(s2, col    )) &&   // (+1, 0)
                (p >= P(s2, col + 1));     // (+1,+1)
            const float msk = mok ? 1.0f : 0.0f;

            const float* rbq = rb + ((h & 1) * C_ + q * CPQ) * CW + col;
            float* op = out + bbase + (size_t)h * W_ + x0 + col;
            #pragma unroll
            for (int i = 0; i < CPQ; i++)
                __stcs(op + (size_t)(q * CPQ + i) * HW_, rbq[i * CW] * msk);
        }
        __syncthreads();   // protect pbq/ph slot SL(h-1) and rb[h&1] reuse
    }
}

// ---------------------------------------------------------------------------
extern "C" void kernel_launch(void* const* d_in, const int* in_sizes, int n_in,
                              void* d_out, int out_size)
{
    const float* points = (const float*)d_in[0];
    float* out = (float*)d_out;

    cudaFuncSetAttribute(fused_nms_pipe4,
                         cudaFuncAttributeMaxDynamicSharedMemorySize,
                         (int)SMEM_BYTES);

    dim3 grid(W_ / CW, H_ / TH, B_);     // (8, 16, 4) = 512 blocks, 4/SM
    fused_nms_pipe4<<<grid, NT, SMEM_BYTES>>>(points, out);
}

// round 13
// speedup vs baseline: 1.3032x; 1.0126x over previous
#include <cuda_runtime.h>
#include <math_constants.h>

#define B_   4
#define C_   84
#define CR_  80          // channels in the max (84 - 4)
#define H_   512
#define W_   512
#define HW_  (H_ * W_)

#define CW   32          // columns per block strip (one warp-lane per column)
#define TH   32          // output rows per block
#define NQ   4           // channel-quarter split: warp q owns channels [q*21, q*21+21)
#define CPQ  21          // C / NQ  (full-row channels per warp)
#define PPQ  20          // CR / NQ (probs-only-row channels per warp)
#define NT   128         // NQ warps * 32 lanes
#define RING 4           // probs ring depth (enables 1 barrier per row)

// ---------------------------------------------------------------------------
// Fused NMS, row-pipelined, register-resident values, 8 blocks/SM.
//
// Block owns a 32-col x 32-row strip of one batch. Warp q owns channel
// quarter q; lane = column. Per output row h (ONE barrier):
//   load row h+1: 21 channels -> regs w[], running 80-ch partial max ->
//     pbq ring slot (h+1)&3; warps 0/1 also compute the two halo-column
//     80-ch maxes (shuffle-reduce) -> ph ring.
//   __syncthreads();
//   mask row h from ring slots (h-1,h,h+1)&3, combining the 4 quarter maxes
//     inline. Reference semantics (window idx, center=4): strict > for the
//     row above + left neighbor, >= for right + row below; zero padding.
//   multiply v[] (row h regs) by mask, streaming stores; v = w.
//
// Ring safety: iter h writes slot (h+1)&3 and reads (h-1..h+1)&3; max warp
// skew is 1 iteration (next write is (h+2)&3, disjoint), so one barrier per
// iteration suffices. Input lines are read exactly once (+2 probs-only halo
// rows per strip, +2 halo columns that ride L2 off neighbor strips).
// ---------------------------------------------------------------------------
__global__ void __launch_bounds__(NT, 8) fused_nms_reg(
    const float* __restrict__ points, float* __restrict__ out)
{
    __shared__ float pbq[RING][NQ][CW];   // per-quarter partial row maxes
    __shared__ float ph[RING][2];         // halo-column combined maxes (L/R)

    const int tid  = threadIdx.x;
    const int q    = tid >> 5;            // warp = channel quarter
    const int col  = tid & 31;            // lane = column in strip
    const int x0   = blockIdx.x * CW;
    const int h0   = blockIdx.y * TH;
    const int b    = blockIdx.z;
    const size_t bbase = (size_t)b * C_ * HW_;

    const float* inb  = points + bbase + x0 + col;
    float*       outb = out    + bbase + x0 + col;

    // halo column for warps 0/1: warp0 -> x0-1, warp1 -> x0+CW
    const int hx = (q == 0) ? (x0 - 1) : (x0 + CW);
    const bool halo_in = (q < 2) && (hx >= 0) && (hx < W_);
    const float* hbase = points + bbase + hx;

    // ---- probs bookkeeping for a loaded/pad row -------------------------
    auto probs_row = [&](int g, float m) {
        const int s = g & 3;
        pbq[s][q][col] = m;
        if (q < 2) {
            float hm = 0.0f;
            if (halo_in && g >= 0 && g < H_) {
                const float* hp = hbase + (size_t)g * W_;
                hm = -CUDART_INF_F;
                #pragma unroll
                for (int k = 0; k < 3; k++) {
                    int c = col + k * 32;
                    if (c < CR_) hm = fmaxf(hm, __ldg(hp + (size_t)c * HW_));
                }
                #pragma unroll
                for (int off = 16; off; off >>= 1)
                    hm = fmaxf(hm, __shfl_xor_sync(0xffffffffu, hm, off));
            }
            if (col == 0) ph[s][q] = hm;
        }
    };

    // ---- probs-only row (halo rows / pad rows) --------------------------
    auto probs_only_row = [&](int g) {
        float m = 0.0f;                   // pad value
        if (g >= 0 && g < H_) {
            const float* rp = inb + (size_t)g * W_;
            m = -CUDART_INF_F;
            #pragma unroll
            for (int i = 0; i < PPQ; i++)  // q*20+i < 80 always
                m = fmaxf(m, __ldg(rp + (size_t)(q * PPQ + i) * HW_));
        }
        probs_row(g, m);
    };

    // combined probs at (ring slot s, strip col c), c in [-1, CW]
    auto P = [&](int s, int c) -> float {
        if (c < 0)   return ph[s][0];
        if (c >= CW) return ph[s][1];
        return fmaxf(fmaxf(pbq[s][0][c], pbq[s][1][c]),
                     fmaxf(pbq[s][2][c], pbq[s][3][c]));
    };

    float v[CPQ], w[CPQ];

    // ---- prologue: probs(h0-1), full(h0) -> v ---------------------------
    probs_only_row(h0 - 1);
    {
        const float* rp = inb + (size_t)h0 * W_;
        float m = -CUDART_INF_F;
        #pragma unroll
        for (int i = 0; i < CPQ; i++) {
            int c = q * CPQ + i;
            float val = __ldg(rp + (size_t)c * HW_);
            v[i] = val;
            if (c < CR_) m = fmaxf(m, val);
        }
        probs_row(h0, m);
    }

    // ---- main pipeline: one barrier per row -----------------------------
    for (int h = h0; h < h0 + TH; h++) {
        const int gn = h + 1;
        if (gn < h0 + TH) {
            const float* rp = inb + (size_t)gn * W_;
            float m = -CUDART_INF_F;
            #pragma unroll
            for (int i = 0; i < CPQ; i++) {
                int c = q * CPQ + i;
                float val = __ldg(rp + (size_t)c * HW_);
                w[i] = val;
                if (c < CR_) m = fmaxf(m, val);
            }
            probs_row(gn, m);
        } else {
            probs_only_row(gn);           // row h0+TH (or pad if == H)
        }
        __syncthreads();

        // mask + multiply row h
        {
            const int s0 = (h - 1) & 3, s1 = h & 3, s2 = (h + 1) & 3;
            const float p = P(s1, col);
            bool mok =
                (p >  P(s0, col - 1)) &&   // (-1,-1)
                (p >  P(s0, col    )) &&   // (-1, 0)
                (p >  P(s0, col + 1)) &&   // (-1,+1)
                (p >  P(s1, col - 1)) &&   // ( 0,-1) left
                (p >= P(s1, col + 1)) &&   // ( 0,+1) right
                (p >= P(s2, col - 1)) &&   // (+1,-1)
                (p >= P(s2, col    )) &&   // (+1, 0)
                (p >= P(s2, col + 1));     // (+1,+1)
            const float msk = mok ? 1.0f : 0.0f;

            float* op = outb + (size_t)h * W_;
            #pragma unroll
            for (int i = 0; i < CPQ; i++)
                __stcs(op + (size_t)(q * CPQ + i) * HW_, v[i] * msk);
        }

        if (gn < h0 + TH) {
            #pragma unroll
            for (int i = 0; i < CPQ; i++) v[i] = w[i];
        }
        // no second barrier: next iteration writes ring slot (h+2)&3,
        // disjoint from the three slots read above; max warp skew = 1 iter.
    }
}

// ---------------------------------------------------------------------------
extern "C" void kernel_launch(void* const* d_in, const int* in_sizes, int n_in,
                              void* d_out, int out_size)
{
    const float* points = (const float*)d_in[0];
    float* out = (float*)d_out;

    dim3 grid(W_ / CW, H_ / TH, B_);   // (16, 16, 4) = 1024 blocks, single wave
    fused_nms_reg<<<grid, NT>>>(points, out);
}